// round 5
// baseline (speedup 1.0000x reference)
#include <cuda_runtime.h>
#include <math.h>

#define N_PTS 65536
#define E_EXP 8
#define F_DIM 236
#define F_PAD 240
#define M_DIM 441
#define HL_N  3
#define TM    96

// TF32 quantization (matches tensor-core TF32 matmul operand rounding).
__device__ __forceinline__ float tf32q(float x) {
    float r;
    asm("cvt.rna.tf32.f32 %0, %1;" : "=f"(r) : "f"(x));
    return r;
}

// -------- device scratch (no runtime allocation allowed) --------
__device__ float g_g2[N_PTS * M_DIM];      // gating hidden2 activations (tf32-rounded)
__device__ int   g_expert[N_PTS];
__device__ int   g_counts[E_EXP];
__device__ int   g_offsets[E_EXP + 1];
__device__ int   g_cursor[E_EXP];
__device__ int   g_perm[N_PTS];

// ---------------- init ----------------
__global__ void k_init() {
    int t = threadIdx.x;
    if (t < E_EXP) g_counts[t] = 0;
}

// ---------------- gating GEMM ----------------
// g2 = relu( relu(x @ moe_W1 + b1) @ moe_W2 + b2 ), all matmuls TF32-quantized.
__global__ void __launch_bounds__(256) k_gate(
    const float* __restrict__ x,
    const float* __restrict__ W1, const float* __restrict__ b1,
    const float* __restrict__ W2, const float* __restrict__ b2)
{
    __shared__ float As[16 * 128];   // [kk][p], tf32-quantized g1
    __shared__ float Bs[16 * 64];    // [kk][c], tf32-quantized W2
    const int tid = threadIdx.x;
    const int ty = tid >> 4, tx = tid & 15;
    const int n0 = blockIdx.y * 128;
    const int j0 = blockIdx.x * 64;

    float acc[8][4];
#pragma unroll
    for (int i = 0; i < 8; i++)
#pragma unroll
        for (int j = 0; j < 4; j++) acc[i][j] = 0.f;

    for (int k0 = 0; k0 < M_DIM; k0 += 16) {
        // A tile: compute g1 on the fly (layer-1 matmul TF32)
#pragma unroll
        for (int q = 0; q < 8; q++) {
            int idx = tid + 256 * q;          // 2048 elements
            int p = idx >> 4, kk = idx & 15;
            int k = k0 + kk;
            float v = 0.f;
            if (k < M_DIM) {
                const float* xr = x + (n0 + p) * 3;
                v = tf32q(xr[0]) * tf32q(W1[k])
                  + tf32q(xr[1]) * tf32q(W1[M_DIM + k])
                  + tf32q(xr[2]) * tf32q(W1[2 * M_DIM + k])
                  + b1[k];
                v = tf32q(fmaxf(v, 0.f));
            }
            As[kk * 128 + p] = v;
        }
        // B tile (quantize W2)
#pragma unroll
        for (int q = 0; q < 4; q++) {
            int idx = tid + 256 * q;          // 1024 elements
            int kk = idx >> 6, c = idx & 63;
            int k = k0 + kk, j = j0 + c;
            Bs[idx] = (k < M_DIM && j < M_DIM) ? tf32q(W2[k * M_DIM + j]) : 0.f;
        }
        __syncthreads();
#pragma unroll
        for (int kk = 0; kk < 16; kk++) {
            float a[8], b[4];
#pragma unroll
            for (int i = 0; i < 8; i++) a[i] = As[kk * 128 + ty * 8 + i];
#pragma unroll
            for (int j = 0; j < 4; j++) b[j] = Bs[kk * 64 + tx * 4 + j];
#pragma unroll
            for (int i = 0; i < 8; i++)
#pragma unroll
                for (int j = 0; j < 4; j++)
                    acc[i][j] = fmaf(a[i], b[j], acc[i][j]);
        }
        __syncthreads();
    }
#pragma unroll
    for (int i = 0; i < 8; i++) {
        int n = n0 + ty * 8 + i;
#pragma unroll
        for (int j = 0; j < 4; j++) {
            int jj = j0 + tx * 4 + j;
            if (jj < M_DIM)
                g_g2[n * M_DIM + jj] = tf32q(fmaxf(acc[i][j] + b2[jj], 0.f));
        }
    }
}

// ---------------- logits + argmax (one warp per point) ----------------
__global__ void __launch_bounds__(256) k_logits(
    const float* __restrict__ W3, const float* __restrict__ b3)
{
    int gw = (blockIdx.x * blockDim.x + threadIdx.x) >> 5;
    int lane = threadIdx.x & 31;
    if (gw >= N_PTS) return;
    const float* g = g_g2 + (size_t)gw * M_DIM;   // already tf32-rounded
    float acc[8];
#pragma unroll
    for (int e = 0; e < 8; e++) acc[e] = 0.f;
    for (int k = lane; k < M_DIM; k += 32) {
        float gv = g[k];
        const float4* w4 = reinterpret_cast<const float4*>(W3 + k * 8);
        float4 wa = w4[0], wb = w4[1];
        acc[0] = fmaf(gv, tf32q(wa.x), acc[0]);
        acc[1] = fmaf(gv, tf32q(wa.y), acc[1]);
        acc[2] = fmaf(gv, tf32q(wa.z), acc[2]);
        acc[3] = fmaf(gv, tf32q(wa.w), acc[3]);
        acc[4] = fmaf(gv, tf32q(wb.x), acc[4]);
        acc[5] = fmaf(gv, tf32q(wb.y), acc[5]);
        acc[6] = fmaf(gv, tf32q(wb.z), acc[6]);
        acc[7] = fmaf(gv, tf32q(wb.w), acc[7]);
    }
#pragma unroll
    for (int e = 0; e < 8; e++) {
#pragma unroll
        for (int s = 16; s > 0; s >>= 1)
            acc[e] += __shfl_xor_sync(0xffffffffu, acc[e], s);
    }
    if (lane == 0) {
        float best = acc[0] + b3[0]; int bi = 0;
#pragma unroll
        for (int e = 1; e < 8; e++) {
            float v = acc[e] + b3[e];
            if (v > best) { best = v; bi = e; }
        }
        g_expert[gw] = bi;
        atomicAdd(&g_counts[bi], 1);
    }
}

// ---------------- scan + KL ----------------
// weights are exactly one-hot -> per-point KL is the constant
// log(1/8) - (1/8)*7*log(1e-10); the reference's tree-reduction/n matches
// this to ~1e-7 relative (division by n shrinks the reduction error).
__global__ void k_scan(float* out, int kl_idx) {
    if (threadIdx.x == 0) {
        int off = 0;
        for (int e = 0; e < E_EXP; e++) {
            g_offsets[e] = off;
            off += g_counts[e];
            g_cursor[e] = 0;
        }
        g_offsets[E_EXP] = off;
        out[kl_idx] = logf(0.125f) - 0.875f * logf(1e-10f);
    }
}

// ---------------- scatter points by expert ----------------
__global__ void k_scatter() {
    int n = blockIdx.x * blockDim.x + threadIdx.x;
    if (n >= N_PTS) return;
    int e = g_expert[n];
    int p = atomicAdd(&g_cursor[e], 1);
    g_perm[g_offsets[e] + p] = n;
}

// ---------------- fused SIREN + decoder ----------------
// One tile-GEMM step: C[96x240] = act(A[96x240(valid 236)] @ W[236x236] + bias)
// act: 0 = sin(30*v), 1 = relu, 2 = none. Outputs stored tf32-rounded.
// NOTE: jj can reach 255 in the jc=3 sweep; the jj < F_PAD guard is
// load-bearing (without it, zeros splatter into the next row's cols 0..15).
__device__ __forceinline__ void tile_gemm(
    const float* __restrict__ W, const float* __restrict__ bias,
    const float* A, float* C, float* Bs, int tid, int act)
{
    const int ty = tid >> 4, tx = tid & 15;
#pragma unroll 1
    for (int jc = 0; jc < 4; jc++) {
        const int j0 = jc * 64;
        float acc[6][4];
#pragma unroll
        for (int i = 0; i < 6; i++)
#pragma unroll
            for (int j = 0; j < 4; j++) acc[i][j] = 0.f;

        for (int k0 = 0; k0 < F_PAD; k0 += 16) {
#pragma unroll
            for (int q = 0; q < 4; q++) {
                int idx = tid + 256 * q;         // 1024
                int kk = idx >> 6, c = idx & 63;
                int k = k0 + kk, j = j0 + c;
                Bs[idx] = (k < F_DIM && j < F_DIM) ? tf32q(W[k * F_DIM + j]) : 0.f;
            }
            __syncthreads();
#pragma unroll
            for (int kk = 0; kk < 16; kk++) {
                float a[6], b[4];
#pragma unroll
                for (int i = 0; i < 6; i++) a[i] = A[(ty * 6 + i) * F_PAD + k0 + kk];
#pragma unroll
                for (int j = 0; j < 4; j++) b[j] = Bs[kk * 64 + tx * 4 + j];
#pragma unroll
                for (int i = 0; i < 6; i++)
#pragma unroll
                    for (int j = 0; j < 4; j++)
                        acc[i][j] = fmaf(a[i], b[j], acc[i][j]);
            }
            __syncthreads();
        }
#pragma unroll
        for (int i = 0; i < 6; i++) {
            int p = ty * 6 + i;
#pragma unroll
            for (int j = 0; j < 4; j++) {
                int jj = j0 + tx * 4 + j;
                if (jj < F_PAD) {                 // <-- the fix
                    float v = 0.f;
                    if (jj < F_DIM) {
                        v = acc[i][j] + bias[jj];
                        if (act == 0)      v = sinf(30.0f * v);
                        else if (act == 1) v = fmaxf(v, 0.f);
                        v = tf32q(v);
                    }
                    C[p * F_PAD + jj] = v;
                }
            }
        }
    }
    __syncthreads();
}

__global__ void __launch_bounds__(256) k_siren(
    const float* __restrict__ x,
    const float* __restrict__ sW1, const float* __restrict__ sb1,
    const float* __restrict__ sWh, const float* __restrict__ sbh,
    const float* __restrict__ sWo, const float* __restrict__ sbo,
    const float* __restrict__ dW1, const float* __restrict__ db1,
    const float* __restrict__ dW2, const float* __restrict__ db2,
    float* __restrict__ out)
{
    extern __shared__ float sm[];
    float* bufA = sm;                       // 96*240
    float* bufB = sm + TM * F_PAD;          // 96*240
    float* Bs   = sm + 2 * TM * F_PAD;      // 16*64
    float* xs   = Bs + 16 * 64;             // 96*4

    const int e = blockIdx.y;
    const int tid = threadIdx.x;
    const int beg = g_offsets[e], end = g_offsets[e + 1];
    const int start = beg + blockIdx.x * TM;
    if (start >= end) return;
    const int npts = min(TM, end - start);

    if (tid < TM) {
        float x0 = 0.f, x1 = 0.f, x2 = 0.f;
        if (tid < npts) {
            int n = g_perm[start + tid];
            x0 = tf32q(x[n * 3]); x1 = tf32q(x[n * 3 + 1]); x2 = tf32q(x[n * 3 + 2]);
        }
        xs[tid * 4] = x0; xs[tid * 4 + 1] = x1; xs[tid * 4 + 2] = x2; xs[tid * 4 + 3] = 0.f;
    }
    __syncthreads();

    // first sine layer: 3 -> 236 (TF32 matmul + f32 bias + sin, store tf32)
    const float* W1e = sW1 + (size_t)e * 3 * F_DIM;
    const float* b1e = sb1 + (size_t)e * F_DIM;
    for (int idx = tid; idx < TM * F_PAD; idx += 256) {
        int p = idx / F_PAD, f = idx - p * F_PAD;
        float v = 0.f;
        if (f < F_DIM) {
            v = xs[p * 4]     * tf32q(W1e[f])
              + xs[p * 4 + 1] * tf32q(W1e[F_DIM + f])
              + xs[p * 4 + 2] * tf32q(W1e[2 * F_DIM + f])
              + b1e[f];
            v = tf32q(sinf(30.0f * v));
        }
        bufA[idx] = v;
    }
    __syncthreads();

    float* A = bufA; float* C = bufB;
    // 3 hidden sine layers
    for (int l = 0; l < HL_N; l++) {
        tile_gemm(sWh + ((size_t)l * E_EXP + e) * F_DIM * F_DIM,
                  sbh + ((size_t)l * E_EXP + e) * F_DIM, A, C, Bs, tid, 0);
        float* t = A; A = C; C = t;
    }
    // siren output layer (no activation)
    tile_gemm(sWo + (size_t)e * F_DIM * F_DIM, sbo + (size_t)e * F_DIM, A, C, Bs, tid, 2);
    { float* t = A; A = C; C = t; }
    // decoder layer 1 (selected expert rows of dec_W1), relu
    tile_gemm(dW1 + (size_t)e * F_DIM * F_DIM, db1, A, C, Bs, tid, 1);
    { float* t = A; A = C; C = t; }

    // decoder layer 2: 236 -> 3 (TF32), scatter to output (NOT quantized)
    for (int t2 = tid; t2 < TM * 3; t2 += 256) {
        int p = t2 / 3, c = t2 - p * 3;
        if (p < npts) {
            const float* ar = A + p * F_PAD;
            float s = db2[c];
            for (int f = 0; f < F_DIM; f++)
                s = fmaf(ar[f], tf32q(dW2[f * 3 + c]), s);
            int n = g_perm[start + p];
            out[n * 3 + c] = s;
        }
    }
}

// ---------------- launch ----------------
extern "C" void kernel_launch(void* const* d_in, const int* in_sizes, int n_in,
                              void* d_out, int out_size)
{
    const float* x   = (const float*)d_in[0];
    const float* sW1 = (const float*)d_in[1];
    const float* sb1 = (const float*)d_in[2];
    const float* sWh = (const float*)d_in[3];
    const float* sbh = (const float*)d_in[4];
    const float* sWo = (const float*)d_in[5];
    const float* sbo = (const float*)d_in[6];
    const float* mW1 = (const float*)d_in[7];
    const float* mb1 = (const float*)d_in[8];
    const float* mW2 = (const float*)d_in[9];
    const float* mb2 = (const float*)d_in[10];
    const float* mW3 = (const float*)d_in[11];
    const float* mb3 = (const float*)d_in[12];
    const float* dW1 = (const float*)d_in[13];
    const float* db1 = (const float*)d_in[14];
    const float* dW2 = (const float*)d_in[15];
    const float* db2 = (const float*)d_in[16];
    float* out = (float*)d_out;

    size_t smem = (size_t)(2 * TM * F_PAD + 16 * 64 + TM * 4) * sizeof(float); // ~189.9 KB
    cudaFuncSetAttribute(k_siren, cudaFuncAttributeMaxDynamicSharedMemorySize, (int)smem);

    k_init<<<1, 32>>>();

    dim3 gG((M_DIM + 63) / 64, N_PTS / 128);   // (7, 512)
    k_gate<<<gG, 256>>>(x, mW1, mb1, mW2, mb2);

    k_logits<<<(N_PTS * 32) / 256, 256>>>(mW3, mb3);   // one warp per point

    k_scan<<<1, 32>>>(out, out_size - 1);

    k_scatter<<<N_PTS / 256, 256>>>();

    dim3 gS((N_PTS + TM - 1) / TM, E_EXP);     // (683, 8); out-of-range tiles exit
    k_siren<<<gS, 256, smem>>>(x, sW1, sb1, sWh, sbh, sWo, sbo,
                               dW1, db1, dW2, db2, out);
}

// round 7
// speedup vs baseline: 3.0225x; 3.0225x over previous
#include <cuda_runtime.h>
#include <math.h>
#include <stdint.h>

#define N_PTS 65536
#define E_EXP 8
#define F_DIM 236
#define M_DIM 441
#define HL_N  3
#define NLAYER 5

// ---- siren tiling ----
#define TMS 64          // points per tile (M)
#define SA  244         // A smem row stride (floats), conflict-free
#define NW  248         // B smem row stride (floats), conflict-free
#define KC  48          // K rows per B chunk (6 ksteps)
#define NCH 5           // chunks per layer (240 = 5*48)
#define NCI (NLAYER * NCH)

// ---- gate tiling ----
#define GN   224        // N tile (2 tiles cover 441<448)
#define GKC  64         // K rows per chunk (8 ksteps)
#define GNCH 7          // 448 = 7*64
#define GSA  68         // A smem stride
#define GNW  232        // B smem stride

// ---------------- helpers ----------------
__device__ __forceinline__ float tf32q(float x) {
    float r; asm("cvt.rna.tf32.f32 %0, %1;" : "=f"(r) : "f"(x)); return r;
}
__device__ __forceinline__ uint32_t smem_u32(const void* p) {
    uint32_t a;
    asm("{ .reg .u64 t; cvta.to.shared.u64 t, %1; cvt.u32.u64 %0, t; }" : "=r"(a) : "l"(p));
    return a;
}
__device__ __forceinline__ void cpa16(uint32_t s, const void* g) {
    asm volatile("cp.async.cg.shared.global [%0], [%1], 16;" :: "r"(s), "l"(g) : "memory");
}
__device__ __forceinline__ void cpa_commit() {
    asm volatile("cp.async.commit_group;" ::: "memory");
}
__device__ __forceinline__ void cpa_wait1() {
    asm volatile("cp.async.wait_group 1;" ::: "memory");
}
__device__ __forceinline__ void cpa_wait0() {
    asm volatile("cp.async.wait_group 0;" ::: "memory");
}
// m16n8k8 tf32 mma: D += A*B. A row-major frag (4 regs), B col-major frag (2 regs).
__device__ __forceinline__ void mma8(float* d, const uint32_t* a, uint32_t b0, uint32_t b1) {
    asm volatile(
        "mma.sync.aligned.m16n8k8.row.col.f32.tf32.tf32.f32 "
        "{%0,%1,%2,%3}, {%4,%5,%6,%7}, {%8,%9}, {%0,%1,%2,%3};"
        : "+f"(d[0]), "+f"(d[1]), "+f"(d[2]), "+f"(d[3])
        : "r"(a[0]), "r"(a[1]), "r"(a[2]), "r"(a[3]), "r"(b0), "r"(b1));
}
__device__ __forceinline__ uint32_t f2u(float f) { return __float_as_uint(f); }

// -------- device scratch --------
__device__ float g_g2[N_PTS * M_DIM];
__device__ int   g_expert[N_PTS];
__device__ int   g_counts[E_EXP];
__device__ int   g_offsets[E_EXP + 1];
__device__ int   g_cursor[E_EXP];
__device__ int   g_perm[N_PTS];
// siren weights: [e][l][k 0..239][n 0..247], tf32-rounded, zero-padded
__device__ float g_Bw[E_EXP * NLAYER * 240 * NW];
// gate W2: [448][448], tf32-rounded, zero-padded
__device__ float g_W2p[448 * 448];

// ---------------- init ----------------
__global__ void k_init() {
    int t = threadIdx.x;
    if (t < E_EXP) g_counts[t] = 0;
}

// ---------------- weight prep ----------------
__global__ void k_prep_siren(const float* __restrict__ sWh,
                             const float* __restrict__ sWo,
                             const float* __restrict__ dW1)
{
    int el = blockIdx.x;                 // 0..39
    int e = el / NLAYER, l = el % NLAYER;
    const float* W;
    if (l < 3)       W = sWh + ((size_t)(l * E_EXP + e)) * F_DIM * F_DIM;
    else if (l == 3) W = sWo + (size_t)e * F_DIM * F_DIM;
    else             W = dW1 + (size_t)e * F_DIM * F_DIM;   // dec_W1 rows e*F..e*F+235
    float* dst = g_Bw + (size_t)el * 240 * NW;
    for (int idx = threadIdx.x; idx < 240 * NW; idx += blockDim.x) {
        int k = idx / NW, n = idx - k * NW;
        dst[idx] = (k < F_DIM && n < F_DIM) ? tf32q(W[k * F_DIM + n]) : 0.f;
    }
}
__global__ void k_prep_gate(const float* __restrict__ W2) {
    for (int idx = blockIdx.x * blockDim.x + threadIdx.x; idx < 448 * 448;
         idx += gridDim.x * blockDim.x) {
        int k = idx / 448, n = idx - k * 448;
        g_W2p[idx] = (k < M_DIM && n < M_DIM) ? tf32q(W2[k * M_DIM + n]) : 0.f;
    }
}

// ---------------- gating GEMM (tf32 mma) ----------------
// g2 = relu(relu(x@W1+b1)@W2+b2); A tile generated on the fly, W2 streamed.
__global__ void __launch_bounds__(256, 1) k_gate(
    const float* __restrict__ x,
    const float* __restrict__ W1, const float* __restrict__ b1,
    const float* __restrict__ b2)
{
    extern __shared__ float sm[];
    float* Asm = sm;                         // 2 x 128 x GSA
    float* Bsm = sm + 2 * 128 * GSA;         // 2 x GKC x GNW
    const int tid = threadIdx.x;
    const int wid = tid >> 5, lane = tid & 31;
    const int n0 = blockIdx.y * 128;         // point rows
    const int cb = blockIdx.x * GN;          // col base (0 or 224)
    const int wrow = (wid & 3) * 32;
    const int wcol = (wid >> 2) * 112;

    float acc[2][14][4];
#pragma unroll
    for (int m = 0; m < 2; m++)
#pragma unroll
        for (int nb = 0; nb < 14; nb++)
#pragma unroll
            for (int j = 0; j < 4; j++) acc[m][nb][j] = 0.f;

    // -- chunk producers --
    auto genA = [&](int ch) {
        float* Ab = Asm + (ch & 1) * 128 * GSA;
        int k0 = ch * GKC;
#pragma unroll
        for (int i = 0; i < 32; i++) {
            int flat = i * 256 + tid;
            int col = flat & 63, row = flat >> 6;
            int k = k0 + col;
            float v = 0.f;
            if (k < M_DIM) {
                const float* xr = x + (n0 + row) * 3;
                v = tf32q(xr[0]) * tf32q(W1[k])
                  + tf32q(xr[1]) * tf32q(W1[M_DIM + k])
                  + tf32q(xr[2]) * tf32q(W1[2 * M_DIM + k])
                  + b1[k];
                v = tf32q(fmaxf(v, 0.f));
            }
            Ab[row * GSA + col] = v;
        }
    };
    auto copyB = [&](int ch) {
        uint32_t dst = smem_u32(Bsm + (ch & 1) * GKC * GNW);
        const char* src = (const char*)(g_W2p + (size_t)(ch * GKC) * 448 + cb);
#pragma unroll
        for (int j = 0; j < 14; j++) {
            int op = j * 256 + tid;          // 3584 ops: 64 rows x 56 x 16B
            int r = op / 56, o = op - r * 56;
            cpa16(dst + (r * GNW) * 4 + o * 16, src + r * 1792 + o * 16);
        }
    };

    genA(0); copyB(0); cpa_commit();
    for (int ch = 0; ch < GNCH; ch++) {
        if (ch + 1 < GNCH) { genA(ch + 1); copyB(ch + 1); cpa_commit(); cpa_wait1(); }
        else cpa_wait0();
        __syncthreads();
        const float* Ab = Asm + (ch & 1) * 128 * GSA;
        const float* Bb = Bsm + (ch & 1) * GKC * GNW;
#pragma unroll
        for (int ks = 0; ks < 8; ks++) {
            int k = ks * 8;
            uint32_t a[2][4];
            int r0 = wrow + (lane >> 2);
#pragma unroll
            for (int m = 0; m < 2; m++) {
                int r = r0 + m * 16;
                a[m][0] = f2u(Ab[r * GSA + k + (lane & 3)]);
                a[m][1] = f2u(Ab[(r + 8) * GSA + k + (lane & 3)]);
                a[m][2] = f2u(Ab[r * GSA + k + 4 + (lane & 3)]);
                a[m][3] = f2u(Ab[(r + 8) * GSA + k + 4 + (lane & 3)]);
            }
#pragma unroll
            for (int nb = 0; nb < 14; nb++) {
                int n = wcol + nb * 8 + (lane >> 2);
                uint32_t b0 = f2u(Bb[(k + (lane & 3)) * GNW + n]);
                uint32_t b1 = f2u(Bb[(k + 4 + (lane & 3)) * GNW + n]);
                mma8(acc[0][nb], a[0], b0, b1);
                mma8(acc[1][nb], a[1], b0, b1);
            }
        }
        __syncthreads();
    }

    // epilogue: g2 = tf32q(relu(acc + b2))
#pragma unroll
    for (int m = 0; m < 2; m++) {
        int r = n0 + wrow + m * 16 + (lane >> 2);
#pragma unroll
        for (int nb = 0; nb < 14; nb++) {
            int col = cb + wcol + nb * 8 + 2 * (lane & 3);
            if (col < M_DIM) {
                g_g2[(size_t)r * M_DIM + col] = tf32q(fmaxf(acc[m][nb][0] + b2[col], 0.f));
                g_g2[(size_t)(r + 8) * M_DIM + col] = tf32q(fmaxf(acc[m][nb][2] + b2[col], 0.f));
            }
            if (col + 1 < M_DIM) {
                g_g2[(size_t)r * M_DIM + col + 1] = tf32q(fmaxf(acc[m][nb][1] + b2[col + 1], 0.f));
                g_g2[(size_t)(r + 8) * M_DIM + col + 1] = tf32q(fmaxf(acc[m][nb][3] + b2[col + 1], 0.f));
            }
        }
    }
}

// ---------------- logits + argmax ----------------
__global__ void __launch_bounds__(256) k_logits(
    const float* __restrict__ W3, const float* __restrict__ b3)
{
    int gw = (blockIdx.x * blockDim.x + threadIdx.x) >> 5;
    int lane = threadIdx.x & 31;
    if (gw >= N_PTS) return;
    const float* g = g_g2 + (size_t)gw * M_DIM;
    float acc[8];
#pragma unroll
    for (int e = 0; e < 8; e++) acc[e] = 0.f;
    for (int k = lane; k < M_DIM; k += 32) {
        float gv = g[k];
        const float4* w4 = reinterpret_cast<const float4*>(W3 + k * 8);
        float4 wa = w4[0], wb = w4[1];
        acc[0] = fmaf(gv, tf32q(wa.x), acc[0]);
        acc[1] = fmaf(gv, tf32q(wa.y), acc[1]);
        acc[2] = fmaf(gv, tf32q(wa.z), acc[2]);
        acc[3] = fmaf(gv, tf32q(wa.w), acc[3]);
        acc[4] = fmaf(gv, tf32q(wb.x), acc[4]);
        acc[5] = fmaf(gv, tf32q(wb.y), acc[5]);
        acc[6] = fmaf(gv, tf32q(wb.z), acc[6]);
        acc[7] = fmaf(gv, tf32q(wb.w), acc[7]);
    }
#pragma unroll
    for (int e = 0; e < 8; e++) {
#pragma unroll
        for (int s = 16; s > 0; s >>= 1)
            acc[e] += __shfl_xor_sync(0xffffffffu, acc[e], s);
    }
    if (lane == 0) {
        float best = acc[0] + b3[0]; int bi = 0;
#pragma unroll
        for (int e = 1; e < 8; e++) {
            float v = acc[e] + b3[e];
            if (v > best) { best = v; bi = e; }
        }
        g_expert[gw] = bi;
        atomicAdd(&g_counts[bi], 1);
    }
}

// ---------------- scan + KL (one-hot => constant) ----------------
__global__ void k_scan(float* out, int kl_idx) {
    if (threadIdx.x == 0) {
        int off = 0;
        for (int e = 0; e < E_EXP; e++) {
            g_offsets[e] = off;
            off += g_counts[e];
            g_cursor[e] = 0;
        }
        g_offsets[E_EXP] = off;
        out[kl_idx] = logf(0.125f) - 0.875f * logf(1e-10f);
    }
}

// ---------------- scatter ----------------
__global__ void k_scatter() {
    int n = blockIdx.x * blockDim.x + threadIdx.x;
    if (n >= N_PTS) return;
    int e = g_expert[n];
    int p = atomicAdd(&g_cursor[e], 1);
    g_perm[g_offsets[e] + p] = n;
}

// ---------------- fused SIREN + decoder (tf32 mma) ----------------
// Per CTA: 64 points. A ping-pong in smem (64 x 240, stride 244). Weights
// streamed in 48-row chunks, double buffered, overlapped with mma.
// 8 warps = 4M x 2N; warp tile 16 x 120 (15 nblocks).
__global__ void __launch_bounds__(256, 1) k_siren(
    const float* __restrict__ x,
    const float* __restrict__ sW1, const float* __restrict__ sb1,
    const float* __restrict__ sbh, const float* __restrict__ sbo,
    const float* __restrict__ db1,
    const float* __restrict__ dW2, const float* __restrict__ db2,
    float* __restrict__ out)
{
    extern __shared__ float sm[];
    float* Bstage = sm + 2 * TMS * SA;       // 2 x KC x NW
    __shared__ float xs[TMS * 3];

    const int e = blockIdx.y;
    const int tid = threadIdx.x;
    const int wid = tid >> 5, lane = tid & 31;
    const int beg = g_offsets[e], end = g_offsets[e + 1];
    const int start = beg + blockIdx.x * TMS;
    if (start >= end) return;
    const int npts = min(TMS, end - start);

    const int wrow = (wid & 3) * 16;
    const int wcoln = (wid >> 2) * 120;
    const float* bwBase = g_Bw + (size_t)e * NLAYER * 240 * NW;

    auto copyB = [&](int ci) {   // ci = global chunk index 0..24
        uint32_t dst = smem_u32(Bstage + (ci & 1) * KC * NW);
        int l = ci / NCH, ch = ci - l * NCH;
        const char* src = (const char*)(bwBase + ((size_t)l * 240 + ch * KC) * NW);
        // KC*NW*4 = 47616 bytes contiguous
#pragma unroll
        for (int j = 0; j < 12; j++) {
            int op = j * 256 + tid;          // need 2976 ops of 16B
            if (op < (KC * NW * 4) / 16)
                cpa16(dst + op * 16, src + op * 16);
        }
    };

    // load coords
    if (tid < TMS) {
        float x0 = 0.f, x1 = 0.f, x2 = 0.f;
        if (tid < npts) {
            int n = g_perm[start + tid];
            x0 = tf32q(x[n * 3]); x1 = tf32q(x[n * 3 + 1]); x2 = tf32q(x[n * 3 + 2]);
        }
        xs[tid * 3] = x0; xs[tid * 3 + 1] = x1; xs[tid * 3 + 2] = x2;
    }
    copyB(0); cpa_commit();
    __syncthreads();

    // first sine layer -> buf0
    {
        const float* W1e = sW1 + (size_t)e * 3 * F_DIM;
        const float* b1e = sb1 + (size_t)e * F_DIM;
        for (int idx = tid; idx < TMS * 240; idx += 256) {
            int row = idx / 240, col = idx - row * 240;
            float v = 0.f;
            if (col < F_DIM) {
                v = xs[row * 3] * tf32q(W1e[col])
                  + xs[row * 3 + 1] * tf32q(W1e[F_DIM + col])
                  + xs[row * 3 + 2] * tf32q(W1e[2 * F_DIM + col])
                  + b1e[col];
                v = tf32q(sinf(30.0f * v));
            }
            sm[row * SA + col] = v;
        }
    }

    int ci = 0;
#pragma unroll 1
    for (int l = 0; l < NLAYER; l++) {
        const float* Ab = sm + (l & 1) * TMS * SA;
        float* Cb = sm + ((l & 1) ^ 1) * TMS * SA;

        float acc[15][4];
#pragma unroll
        for (int nb = 0; nb < 15; nb++)
#pragma unroll
            for (int j = 0; j < 4; j++) acc[nb][j] = 0.f;

#pragma unroll 1
        for (int ch = 0; ch < NCH; ch++, ci++) {
            if (ci + 1 < NCI) { copyB(ci + 1); cpa_commit(); cpa_wait1(); }
            else cpa_wait0();
            __syncthreads();
            const float* Bb = Bstage + (ci & 1) * KC * NW;
#pragma unroll
            for (int ks = 0; ks < KC / 8; ks++) {
                int kg = ch * KC + ks * 8;   // global k for A
                int kl = ks * 8;             // local k for B chunk
                uint32_t a[4];
                int r = wrow + (lane >> 2);
                a[0] = f2u(Ab[r * SA + kg + (lane & 3)]);
                a[1] = f2u(Ab[(r + 8) * SA + kg + (lane & 3)]);
                a[2] = f2u(Ab[r * SA + kg + 4 + (lane & 3)]);
                a[3] = f2u(Ab[(r + 8) * SA + kg + 4 + (lane & 3)]);
#pragma unroll
                for (int nb = 0; nb < 15; nb++) {
                    int n = wcoln + nb * 8 + (lane >> 2);
                    uint32_t b0 = f2u(Bb[(kl + (lane & 3)) * NW + n]);
                    uint32_t b1 = f2u(Bb[(kl + 4 + (lane & 3)) * NW + n]);
                    mma8(acc[nb], a, b0, b1);
                }
            }
            __syncthreads();
        }

        // epilogue: bias + activation -> Cb
        const float* bias = (l < 3) ? (sbh + (size_t)(l * E_EXP + e) * F_DIM)
                          : (l == 3) ? (sbo + (size_t)e * F_DIM) : db1;
        int r = wrow + (lane >> 2);
#pragma unroll
        for (int nb = 0; nb < 15; nb++) {
            int col = wcoln + nb * 8 + 2 * (lane & 3);
#pragma unroll
            for (int h = 0; h < 2; h++) {        // h=0: rows r, h=1: rows r+8
                float v0 = 0.f, v1 = 0.f;
                if (col < F_DIM) {
                    v0 = acc[nb][h * 2] + bias[col];
                    if (l < 3)       v0 = sinf(30.0f * v0);
                    else if (l == 4) v0 = fmaxf(v0, 0.f);
                    v0 = tf32q(v0);
                }
                if (col + 1 < F_DIM) {
                    v1 = acc[nb][h * 2 + 1] + bias[col + 1];
                    if (l < 3)       v1 = sinf(30.0f * v1);
                    else if (l == 4) v1 = fmaxf(v1, 0.f);
                    v1 = tf32q(v1);
                }
                *reinterpret_cast<float2*>(&Cb[(r + h * 8) * SA + col]) = make_float2(v0, v1);
            }
        }
        __syncthreads();
    }

    // dec2: 236 -> 3 from buf1
    const float* Af = sm + TMS * SA;
    if (tid < TMS * 3) {
        int p = tid / 3, c = tid - p * 3;
        if (p < npts) {
            float s = db2[c];
            for (int f = 0; f < F_DIM; f++)
                s = fmaf(Af[p * SA + f], tf32q(dW2[f * 3 + c]), s);
            int n = g_perm[start + p];
            out[n * 3 + c] = s;
        }
    }
}

// ---------------- launch ----------------
extern "C" void kernel_launch(void* const* d_in, const int* in_sizes, int n_in,
                              void* d_out, int out_size)
{
    const float* x   = (const float*)d_in[0];
    const float* sW1 = (const float*)d_in[1];
    const float* sb1 = (const float*)d_in[2];
    const float* sWh = (const float*)d_in[3];
    const float* sbh = (const float*)d_in[4];
    const float* sWo = (const float*)d_in[5];
    const float* sbo = (const float*)d_in[6];
    const float* mW1 = (const float*)d_in[7];
    const float* mb1 = (const float*)d_in[8];
    const float* mW2 = (const float*)d_in[9];
    const float* mb2 = (const float*)d_in[10];
    const float* mW3 = (const float*)d_in[11];
    const float* mb3 = (const float*)d_in[12];
    const float* dW1 = (const float*)d_in[13];
    const float* db1 = (const float*)d_in[14];
    const float* dW2 = (const float*)d_in[15];
    const float* db2 = (const float*)d_in[16];
    float* out = (float*)d_out;

    size_t smem_gate  = (size_t)(2 * 128 * GSA + 2 * GKC * GNW) * 4;   // 188416
    size_t smem_siren = (size_t)(2 * TMS * SA + 2 * KC * NW) * 4;      // 220160
    cudaFuncSetAttribute(k_gate,  cudaFuncAttributeMaxDynamicSharedMemorySize, (int)smem_gate);
    cudaFuncSetAttribute(k_siren, cudaFuncAttributeMaxDynamicSharedMemorySize, (int)smem_siren);

    k_init<<<1, 32>>>();
    k_prep_siren<<<E_EXP * NLAYER, 256>>>(sWh, sWo, dW1);
    k_prep_gate<<<128, 256>>>(mW2);

    dim3 gG(2, N_PTS / 128);                 // (ntile, mtile)
    k_gate<<<gG, 256, smem_gate>>>(x, mW1, mb1, mb2);

    k_logits<<<(N_PTS * 32) / 256, 256>>>(mW3, mb3);

    k_scan<<<1, 32>>>(out, out_size - 1);

    k_scatter<<<N_PTS / 256, 256>>>();

    dim3 gS((N_PTS + TMS - 1) / TMS, E_EXP); // (1024, 8), extras exit
    k_siren<<<gS, 256, smem_siren>>>(x, sW1, sb1, sbh, sbo, db1, dW2, db2, out);
}

// round 8
// speedup vs baseline: 3.1622x; 1.0462x over previous
#include <cuda_runtime.h>
#include <math.h>
#include <stdint.h>

#define N_PTS 65536
#define E_EXP 8
#define F_DIM 236
#define M_DIM 441
#define NLAYER 5

// ---- siren tiling ----
#define TMS   64            // points per CTA
#define SKS   30            // total ksteps (K padded 240)
#define SKC   5             // ksteps per B chunk
#define SNCH  6             // chunks per layer
#define SNPAD 260           // B n-pad (f2 row len), 260%16==4 -> bank-friendly
#define SSLAB (SKC*4*SNPAD) // 5200 f2 per B slab
#define SABUF (SKS*TMS*4)   // 7680 f2 per A buffer

// ---- gate tiling ----
#define GM    128
#define GNT   112
#define GKC   4             // ksteps per chunk
#define GNCH  14            // K padded 448
#define GNPAD 116
#define GASLAB (GKC*GM*4)   // 2048 f2
#define GBSLAB (GKC*4*GNPAD) // 1856 f2

// ---------------- helpers ----------------
__device__ __forceinline__ float tf32q(float x) {
    float r; asm("cvt.rna.tf32.f32 %0, %1;" : "=f"(r) : "f"(x)); return r;
}
__device__ __forceinline__ uint32_t smem_u32(const void* p) {
    uint32_t a;
    asm("{ .reg .u64 t; cvta.to.shared.u64 t, %1; cvt.u32.u64 %0, t; }" : "=r"(a) : "l"(p));
    return a;
}
__device__ __forceinline__ void cpa16(uint32_t s, const void* g) {
    asm volatile("cp.async.cg.shared.global [%0], [%1], 16;" :: "r"(s), "l"(g) : "memory");
}
__device__ __forceinline__ void cpa_commit() { asm volatile("cp.async.commit_group;" ::: "memory"); }
__device__ __forceinline__ void cpa_wait1()  { asm volatile("cp.async.wait_group 1;" ::: "memory"); }
__device__ __forceinline__ void cpa_wait0()  { asm volatile("cp.async.wait_group 0;" ::: "memory"); }
__device__ __forceinline__ void mma8(float* d, const uint32_t* a, uint32_t b0, uint32_t b1) {
    asm volatile(
        "mma.sync.aligned.m16n8k8.row.col.f32.tf32.tf32.f32 "
        "{%0,%1,%2,%3}, {%4,%5,%6,%7}, {%8,%9}, {%0,%1,%2,%3};"
        : "+f"(d[0]), "+f"(d[1]), "+f"(d[2]), "+f"(d[3])
        : "r"(a[0]), "r"(a[1]), "r"(a[2]), "r"(a[3]), "r"(b0), "r"(b1));
}
__device__ __forceinline__ uint32_t f2u(float f) { return __float_as_uint(f); }

// -------- device scratch --------
__device__ float g_g2[N_PTS * M_DIM];
__device__ int   g_expert[N_PTS];
__device__ int   g_counts[E_EXP];
__device__ int   g_offsets[E_EXP + 1];
__device__ int   g_cursor[E_EXP];
__device__ int   g_perm[N_PTS];
// g1 activations, A-fragment-paired: [band512][kt56][r128][c4] float2
__device__ __align__(16) float g_g1p[(size_t)512 * 56 * GM * 4 * 2];
// gate W2 paired: [kc14][ks4][c4][n448] float2
__device__ __align__(16) float g_W2pp[14 * 4 * 4 * 448 * 2];
// siren weights paired: [e][l][ch6][ks5][c4][n260] float2
__device__ __align__(16) float g_Bws[E_EXP * NLAYER * SNCH * SSLAB * 2];

// ---------------- init ----------------
__global__ void k_init() {
    int t = threadIdx.x;
    if (t < E_EXP) g_counts[t] = 0;
}

// ---------------- g1 precompute (paired A layout) ----------------
__global__ void __launch_bounds__(256) k_g1(
    const float* __restrict__ x, const float* __restrict__ W1, const float* __restrict__ b1)
{
    __shared__ float xs[GM * 3];
    int band = blockIdx.x;
    for (int i = threadIdx.x; i < GM * 3; i += 256) xs[i] = tf32q(x[band * GM * 3 + i]);
    __syncthreads();
    float2* dst = ((float2*)g_g1p) + (size_t)band * (56 * GM * 4);
    for (int s = threadIdx.x; s < 56 * GM * 4; s += 256) {
        int c = s & 3, r = (s >> 2) & 127, kt = s >> 9;    // kt 0..55
        int k0 = kt * 8 + c;
        const float* xr = xs + r * 3;
        float2 v; v.x = 0.f; v.y = 0.f;
        if (k0 < M_DIM)
            v.x = tf32q(fmaxf(xr[0] * tf32q(W1[k0]) + xr[1] * tf32q(W1[M_DIM + k0])
                            + xr[2] * tf32q(W1[2 * M_DIM + k0]) + b1[k0], 0.f));
        int k1 = k0 + 4;
        if (k1 < M_DIM)
            v.y = tf32q(fmaxf(xr[0] * tf32q(W1[k1]) + xr[1] * tf32q(W1[M_DIM + k1])
                            + xr[2] * tf32q(W1[2 * M_DIM + k1]) + b1[k1], 0.f));
        dst[s] = v;
    }
}

// ---------------- weight preps (paired B layouts) ----------------
__global__ void k_prep_gateB(const float* __restrict__ W2) {
    float2* dst = (float2*)g_W2pp;
    for (int s = blockIdx.x * blockDim.x + threadIdx.x; s < 14 * 4 * 4 * 448;
         s += gridDim.x * blockDim.x) {
        int n = s % 448, c = (s / 448) & 3, ks = (s / 1792) & 3, kc = s / 7168;
        int k0 = (kc * 4 + ks) * 8 + c;
        float2 v; v.x = 0.f; v.y = 0.f;
        if (n < M_DIM) {
            if (k0 < M_DIM)     v.x = tf32q(W2[(size_t)k0 * M_DIM + n]);
            if (k0 + 4 < M_DIM) v.y = tf32q(W2[(size_t)(k0 + 4) * M_DIM + n]);
        }
        dst[s] = v;
    }
}
__global__ void k_prep_siren(const float* __restrict__ sWh,
                             const float* __restrict__ sWo,
                             const float* __restrict__ dW1)
{
    int el = blockIdx.x;                  // 0..39
    int e = el / NLAYER, l = el % NLAYER;
    const float* W;
    if (l < 3)       W = sWh + ((size_t)(l * E_EXP + e)) * F_DIM * F_DIM;
    else if (l == 3) W = sWo + (size_t)e * F_DIM * F_DIM;
    else             W = dW1 + (size_t)e * F_DIM * F_DIM;
    float2* dst = ((float2*)g_Bws) + (size_t)el * (SNCH * SSLAB);
    for (int s = threadIdx.x; s < SNCH * SSLAB; s += blockDim.x) {
        int n = s % SNPAD, c = (s / SNPAD) & 3, ks = (s / (SNPAD * 4)) % 5, ch = s / SSLAB;
        int k0 = (ch * SKC + ks) * 8 + c;
        float2 v; v.x = 0.f; v.y = 0.f;
        if (n < F_DIM) {
            if (k0 < F_DIM)     v.x = tf32q(W[k0 * F_DIM + n]);
            if (k0 + 4 < F_DIM) v.y = tf32q(W[(k0 + 4) * F_DIM + n]);
        }
        dst[s] = v;
    }
}

// ---------------- gating GEMM (tf32 mma, paired frags) ----------------
__global__ void __launch_bounds__(256, 2) k_gate(const float* __restrict__ b2)
{
    extern __shared__ float smf[];
    float2* Af = (float2*)smf;                 // 2 x GASLAB
    float2* Bf = ((float2*)smf) + 2 * GASLAB;  // 2 x GBSLAB
    const int tid = threadIdx.x;
    const int wid = tid >> 5, lane = tid & 31;
    const int r4 = lane >> 2, c4 = lane & 3;
    const int band = blockIdx.y;
    const int cb = blockIdx.x * GNT;
    const int wrow = (wid & 3) * 32;
    const int wcol = (wid >> 2) * 56;

    float acc[2][7][4];
#pragma unroll
    for (int m = 0; m < 2; m++)
#pragma unroll
        for (int nb = 0; nb < 7; nb++)
#pragma unroll
            for (int j = 0; j < 4; j++) acc[m][nb][j] = 0.f;

    auto copyA = [&](int ch) {
        uint32_t dst = smem_u32(Af + (ch & 1) * GASLAB);
        const char* src = (const char*)g_g1p + ((size_t)band * GNCH + ch) * (GASLAB * 8);
#pragma unroll
        for (int j = 0; j < 4; j++) {
            int op = j * 256 + tid;            // 1024 ops x 16B
            cpa16(dst + op * 16, src + op * 16);
        }
    };
    auto copyB = [&](int ch) {
        uint32_t dst = smem_u32(Bf + (ch & 1) * GBSLAB);
        const float2* srcb = ((const float2*)g_W2pp) + (size_t)ch * (GKC * 4 * 448) + cb;
#pragma unroll
        for (int j = 0; j < 4; j++) {
            int op = j * 256 + tid;            // 896 ops (16 rows x 56)
            if (op < 896) {
                int row = op / 56, off = op % 56;
                cpa16(dst + (row * GNPAD + off * 2) * 8,
                      (const char*)(srcb + (size_t)row * 448) + off * 16);
            }
        }
    };

    copyA(0); copyB(0); cpa_commit();
#pragma unroll 1
    for (int ch = 0; ch < GNCH; ch++) {
        if (ch + 1 < GNCH) { copyA(ch + 1); copyB(ch + 1); cpa_commit(); cpa_wait1(); }
        else cpa_wait0();
        __syncthreads();
        const float2* Ab = Af + (ch & 1) * GASLAB;
        const float2* Bb = Bf + (ch & 1) * GBSLAB;
#pragma unroll
        for (int ks = 0; ks < GKC; ks++) {
            uint32_t a[2][4];
#pragma unroll
            for (int mb = 0; mb < 2; mb++) {
                int r = wrow + 16 * mb + r4;
                float2 p = Ab[(ks * GM + r) * 4 + c4];
                float2 q = Ab[(ks * GM + r + 8) * 4 + c4];
                a[mb][0] = f2u(p.x); a[mb][1] = f2u(q.x);
                a[mb][2] = f2u(p.y); a[mb][3] = f2u(q.y);
            }
#pragma unroll
            for (int nb = 0; nb < 7; nb++) {
                float2 b = Bb[(ks * 4 + c4) * GNPAD + wcol + nb * 8 + r4];
                mma8(acc[0][nb], a[0], f2u(b.x), f2u(b.y));
                mma8(acc[1][nb], a[1], f2u(b.x), f2u(b.y));
            }
        }
        __syncthreads();
    }

    // epilogue: g2 = tf32q(relu(acc + b2))
#pragma unroll
    for (int mb = 0; mb < 2; mb++) {
        int r = band * GM + wrow + 16 * mb + r4;
#pragma unroll
        for (int nb = 0; nb < 7; nb++) {
            int col = cb + wcol + nb * 8 + 2 * c4;
            if (col < M_DIM) {
                g_g2[(size_t)r * M_DIM + col]       = tf32q(fmaxf(acc[mb][nb][0] + b2[col], 0.f));
                g_g2[(size_t)(r + 8) * M_DIM + col] = tf32q(fmaxf(acc[mb][nb][2] + b2[col], 0.f));
            }
            if (col + 1 < M_DIM) {
                g_g2[(size_t)r * M_DIM + col + 1]       = tf32q(fmaxf(acc[mb][nb][1] + b2[col + 1], 0.f));
                g_g2[(size_t)(r + 8) * M_DIM + col + 1] = tf32q(fmaxf(acc[mb][nb][3] + b2[col + 1], 0.f));
            }
        }
    }
}

// ---------------- logits + argmax ----------------
__global__ void __launch_bounds__(256) k_logits(
    const float* __restrict__ W3, const float* __restrict__ b3)
{
    int gw = (blockIdx.x * blockDim.x + threadIdx.x) >> 5;
    int lane = threadIdx.x & 31;
    if (gw >= N_PTS) return;
    const float* g = g_g2 + (size_t)gw * M_DIM;
    float acc[8];
#pragma unroll
    for (int e = 0; e < 8; e++) acc[e] = 0.f;
    for (int k = lane; k < M_DIM; k += 32) {
        float gv = g[k];
        const float4* w4 = reinterpret_cast<const float4*>(W3 + k * 8);
        float4 wa = w4[0], wb = w4[1];
        acc[0] = fmaf(gv, tf32q(wa.x), acc[0]);
        acc[1] = fmaf(gv, tf32q(wa.y), acc[1]);
        acc[2] = fmaf(gv, tf32q(wa.z), acc[2]);
        acc[3] = fmaf(gv, tf32q(wa.w), acc[3]);
        acc[4] = fmaf(gv, tf32q(wb.x), acc[4]);
        acc[5] = fmaf(gv, tf32q(wb.y), acc[5]);
        acc[6] = fmaf(gv, tf32q(wb.z), acc[6]);
        acc[7] = fmaf(gv, tf32q(wb.w), acc[7]);
    }
#pragma unroll
    for (int e = 0; e < 8; e++) {
#pragma unroll
        for (int s = 16; s > 0; s >>= 1)
            acc[e] += __shfl_xor_sync(0xffffffffu, acc[e], s);
    }
    if (lane == 0) {
        float best = acc[0] + b3[0]; int bi = 0;
#pragma unroll
        for (int e = 1; e < 8; e++) {
            float v = acc[e] + b3[e];
            if (v > best) { best = v; bi = e; }
        }
        g_expert[gw] = bi;
        atomicAdd(&g_counts[bi], 1);
    }
}

// ---------------- scan + KL (one-hot => constant) ----------------
__global__ void k_scan(float* out, int kl_idx) {
    if (threadIdx.x == 0) {
        int off = 0;
        for (int e = 0; e < E_EXP; e++) {
            g_offsets[e] = off;
            off += g_counts[e];
            g_cursor[e] = 0;
        }
        g_offsets[E_EXP] = off;
        out[kl_idx] = logf(0.125f) - 0.875f * logf(1e-10f);
    }
}

// ---------------- scatter ----------------
__global__ void k_scatter() {
    int n = blockIdx.x * blockDim.x + threadIdx.x;
    if (n >= N_PTS) return;
    int e = g_expert[n];
    int p = atomicAdd(&g_cursor[e], 1);
    g_perm[g_offsets[e] + p] = n;
}

// ---------------- fused SIREN + decoder (tf32 mma, frag-resident A) ----------------
__global__ void __launch_bounds__(256, 1) k_siren(
    const float* __restrict__ x,
    const float* __restrict__ sW1, const float* __restrict__ sb1,
    const float* __restrict__ sbh, const float* __restrict__ sbo,
    const float* __restrict__ db1,
    const float* __restrict__ dW2, const float* __restrict__ db2,
    float* __restrict__ out)
{
    extern __shared__ float smf[];
    float2* Af2 = (float2*)smf;              // 2 x SABUF
    float2* Bf2 = Af2 + 2 * SABUF;           // 2 x SSLAB
    __shared__ float xs[TMS * 3];
    __shared__ float part[4][TMS][3];

    const int e = blockIdx.y;
    const int tid = threadIdx.x;
    const int wid = tid >> 5, lane = tid & 31;
    const int r4 = lane >> 2, c4 = lane & 3;
    const int beg = g_offsets[e], end = g_offsets[e + 1];
    const int start = beg + blockIdx.x * TMS;
    if (start >= end) return;
    const int npts = min(TMS, end - start);

    const int wrow = (wid & 1) * 32;
    const int wcol = (wid >> 1) * 64;
    const float2* bsrc = ((const float2*)g_Bws) + (size_t)e * (NLAYER * SNCH * SSLAB);

    auto copyB = [&](int ci) {
        uint32_t dst = smem_u32(Bf2 + (ci & 1) * SSLAB);
        const char* src = (const char*)(bsrc + (size_t)ci * SSLAB);
#pragma unroll
        for (int j = 0; j < 11; j++) {
            int op = j * 256 + tid;           // 2600 x 16B
            if (op < 2600) cpa16(dst + op * 16, src + op * 16);
        }
    };

    if (tid < TMS) {
        float x0 = 0.f, x1 = 0.f, x2 = 0.f;
        if (tid < npts) {
            int n = g_perm[start + tid];
            x0 = tf32q(x[n * 3]); x1 = tf32q(x[n * 3 + 1]); x2 = tf32q(x[n * 3 + 2]);
        }
        xs[tid * 3] = x0; xs[tid * 3 + 1] = x1; xs[tid * 3 + 2] = x2;
    }
    copyB(0); cpa_commit();
    __syncthreads();

    // first sine layer -> A buffer 0 (fragment-paired layout)
    {
        const float* W1e = sW1 + (size_t)e * 3 * F_DIM;
        const float* b1e = sb1 + (size_t)e * F_DIM;
        float* A0 = (float*)Af2;
        for (int idx = tid; idx < TMS * 240; idx += 256) {
            int row = idx / 240, col = idx - row * 240;
            float v = 0.f;
            if (col < F_DIM) {
                v = xs[row * 3] * tf32q(W1e[col])
                  + xs[row * 3 + 1] * tf32q(W1e[F_DIM + col])
                  + xs[row * 3 + 2] * tf32q(W1e[2 * F_DIM + col])
                  + b1e[col];
                v = tf32q(sinf(30.0f * v));
            }
            A0[(((col >> 3) * TMS + row) * 4 + (col & 3)) * 2 + ((col >> 2) & 1)] = v;
        }
    }

    int ci = 0;
#pragma unroll 1
    for (int l = 0; l < NLAYER; l++) {
        const float2* Ab = Af2 + (l & 1) * SABUF;
        float* Cw = (float*)(Af2 + ((l & 1) ^ 1) * SABUF);

        float acc[2][8][4];
#pragma unroll
        for (int m = 0; m < 2; m++)
#pragma unroll
            for (int nb = 0; nb < 8; nb++)
#pragma unroll
                for (int j = 0; j < 4; j++) acc[m][nb][j] = 0.f;

#pragma unroll 1
        for (int chn = 0; chn < SNCH; chn++, ci++) {
            if (ci + 1 < NLAYER * SNCH) { copyB(ci + 1); cpa_commit(); cpa_wait1(); }
            else cpa_wait0();
            __syncthreads();
            const float2* Bb = Bf2 + (ci & 1) * SSLAB;
#pragma unroll
            for (int ksl = 0; ksl < SKC; ksl++) {
                int kg = chn * SKC + ksl;
                uint32_t a[2][4];
#pragma unroll
                for (int mb = 0; mb < 2; mb++) {
                    int r = wrow + 16 * mb + r4;
                    float2 p = Ab[(kg * TMS + r) * 4 + c4];
                    float2 q = Ab[(kg * TMS + r + 8) * 4 + c4];
                    a[mb][0] = f2u(p.x); a[mb][1] = f2u(q.x);
                    a[mb][2] = f2u(p.y); a[mb][3] = f2u(q.y);
                }
#pragma unroll
                for (int nb = 0; nb < 8; nb++) {
                    float2 b = Bb[(ksl * 4 + c4) * SNPAD + wcol + nb * 8 + r4];
                    mma8(acc[0][nb], a[0], f2u(b.x), f2u(b.y));
                    mma8(acc[1][nb], a[1], f2u(b.x), f2u(b.y));
                }
            }
            __syncthreads();
        }

        if (l < 4) {
            // bias + activation -> next A buffer (fragment-paired layout)
            const float* bias = (l < 3) ? (sbh + (size_t)(l * E_EXP + e) * F_DIM)
                                        : (sbo + (size_t)e * F_DIM);
#pragma unroll
            for (int mb = 0; mb < 2; mb++) {
                int r = wrow + 16 * mb + r4;
#pragma unroll
                for (int nb = 0; nb < 8; nb++) {
                    int j0 = wcol + nb * 8 + 2 * c4;
                    if (j0 >= 240) continue;
                    int kt = j0 >> 3, cA = j0 & 3, h = (j0 >> 2) & 1;
#pragma unroll
                    for (int hr = 0; hr < 2; hr++) {
                        int row = r + 8 * hr;
                        float v0 = 0.f, v1 = 0.f;
                        if (j0 < F_DIM) {
                            v0 = acc[mb][nb][2 * hr] + bias[j0];
                            if (l < 3) v0 = sinf(30.0f * v0);
                            v0 = tf32q(v0);
                        }
                        if (j0 + 1 < F_DIM) {
                            v1 = acc[mb][nb][2 * hr + 1] + bias[j0 + 1];
                            if (l < 3) v1 = sinf(30.0f * v1);
                            v1 = tf32q(v1);
                        }
                        int base = ((kt * TMS + row) * 4 + cA) * 2 + h;
                        Cw[base] = v0;
                        Cw[base + 2] = v1;   // (cA+1) slot
                    }
                }
            }
            __syncthreads();
        } else {
            // dec1 (relu) + dec2 (236->3) fused from registers
            float s[4][3];
#pragma unroll
            for (int ri = 0; ri < 4; ri++)
#pragma unroll
                for (int o = 0; o < 3; o++) s[ri][o] = 0.f;
#pragma unroll
            for (int mb = 0; mb < 2; mb++) {
#pragma unroll
                for (int nb = 0; nb < 8; nb++) {
                    int j0 = wcol + nb * 8 + 2 * c4;
                    if (j0 >= F_DIM) continue;
#pragma unroll
                    for (int hr = 0; hr < 2; hr++) {
                        int ri = mb * 2 + hr;
                        float a0 = tf32q(fmaxf(acc[mb][nb][2 * hr] + db1[j0], 0.f));
                        s[ri][0] = fmaf(a0, tf32q(dW2[j0 * 3 + 0]), s[ri][0]);
                        s[ri][1] = fmaf(a0, tf32q(dW2[j0 * 3 + 1]), s[ri][1]);
                        s[ri][2] = fmaf(a0, tf32q(dW2[j0 * 3 + 2]), s[ri][2]);
                        if (j0 + 1 < F_DIM) {
                            float a1 = tf32q(fmaxf(acc[mb][nb][2 * hr + 1] + db1[j0 + 1], 0.f));
                            s[ri][0] = fmaf(a1, tf32q(dW2[(j0 + 1) * 3 + 0]), s[ri][0]);
                            s[ri][1] = fmaf(a1, tf32q(dW2[(j0 + 1) * 3 + 1]), s[ri][1]);
                            s[ri][2] = fmaf(a1, tf32q(dW2[(j0 + 1) * 3 + 2]), s[ri][2]);
                        }
                    }
                }
            }
#pragma unroll
            for (int ri = 0; ri < 4; ri++)
#pragma unroll
                for (int o = 0; o < 3; o++) {
                    float v = s[ri][o];
                    v += __shfl_xor_sync(0xffffffffu, v, 1);
                    v += __shfl_xor_sync(0xffffffffu, v, 2);
                    s[ri][o] = v;
                }
            int ng = wid >> 1;
            if (c4 == 0) {
#pragma unroll
                for (int ri = 0; ri < 4; ri++) {
                    int row = wrow + 16 * (ri >> 1) + r4 + 8 * (ri & 1);
#pragma unroll
                    for (int o = 0; o < 3; o++) part[ng][row][o] = s[ri][o];
                }
            }
            __syncthreads();
            if (tid < TMS * 3) {
                int p = tid / 3, o = tid - p * 3;
                if (p < npts) {
                    float v = db2[o] + part[0][p][o] + part[1][p][o]
                            + part[2][p][o] + part[3][p][o];
                    out[g_perm[start + p] * 3 + o] = v;
                }
            }
        }
    }
}

// ---------------- launch ----------------
extern "C" void kernel_launch(void* const* d_in, const int* in_sizes, int n_in,
                              void* d_out, int out_size)
{
    const float* x   = (const float*)d_in[0];
    const float* sW1 = (const float*)d_in[1];
    const float* sb1 = (const float*)d_in[2];
    const float* sWh = (const float*)d_in[3];
    const float* sbh = (const float*)d_in[4];
    const float* sWo = (const float*)d_in[5];
    const float* sbo = (const float*)d_in[6];
    const float* mW1 = (const float*)d_in[7];
    const float* mb1 = (const float*)d_in[8];
    const float* mW2 = (const float*)d_in[9];
    const float* mb2 = (const float*)d_in[10];
    const float* mW3 = (const float*)d_in[11];
    const float* mb3 = (const float*)d_in[12];
    const float* dW1 = (const float*)d_in[13];
    const float* db1 = (const float*)d_in[14];
    const float* dW2 = (const float*)d_in[15];
    const float* db2 = (const float*)d_in[16];
    float* out = (float*)d_out;

    size_t smem_gate  = (size_t)(2 * GASLAB + 2 * GBSLAB) * 8;  // 62464 B
    size_t smem_siren = (size_t)(2 * SABUF + 2 * SSLAB) * 8;    // 206080 B
    cudaFuncSetAttribute(k_gate,  cudaFuncAttributeMaxDynamicSharedMemorySize, (int)smem_gate);
    cudaFuncSetAttribute(k_siren, cudaFuncAttributeMaxDynamicSharedMemorySize, (int)smem_siren);

    k_init<<<1, 32>>>();
    k_g1<<<512, 256>>>(x, mW1, mb1);
    k_prep_gateB<<<128, 256>>>(mW2);
    k_prep_siren<<<E_EXP * NLAYER, 256>>>(sWh, sWo, dW1);

    dim3 gG(4, 512);                         // (N tiles, bands)
    k_gate<<<gG, 256, smem_gate>>>(mb2);

    k_logits<<<(N_PTS * 32) / 256, 256>>>(mW3, mb3);

    k_scan<<<1, 32>>>(out, out_size - 1);

    k_scatter<<<N_PTS / 256, 256>>>();

    dim3 gS((N_PTS + TMS - 1) / TMS, E_EXP); // (1024, 8), extras exit
    k_siren<<<gS, 256, smem_siren>>>(x, sW1, sb1, sbh, sbo, db1, dW2, db2, out);
}

// round 9
// speedup vs baseline: 3.5533x; 1.1237x over previous
#include <cuda_runtime.h>
#include <math.h>
#include <stdint.h>

#define N_PTS 65536
#define E_EXP 8
#define F_DIM 236
#define M_DIM 441
#define NLAYER 5

// ---- siren tiling ----
#define TMS   64            // points per CTA
#define SKS   30            // total ksteps (K padded 240)
#define SKC   5             // ksteps per B chunk
#define SNCH  6             // chunks per layer
#define SNPAD 260           // B n-pad (f2 row len)
#define SSLAB (SKC*4*SNPAD) // 5200 f2 per B slab (41600 B)
#define SABUF (SKS*TMS*4)   // 7680 f2 per A buffer
#define SBYTES (SSLAB*8)

// ---- gate tiling ----
#define GM    128
#define GNT   112
#define GKC   4             // ksteps per chunk
#define GNCH  14            // K padded 448
#define GNPAD 116
#define GASLAB (GKC*GM*4)    // 2048 f2 (16384 B)
#define GBSLAB (GKC*4*GNPAD) // 1856 f2 (14848 B)
#define GBYTES (GASLAB*8 + GBSLAB*8)

// ---------------- helpers ----------------
__device__ __forceinline__ float tf32q(float x) {
    float r; asm("cvt.rna.tf32.f32 %0, %1;" : "=f"(r) : "f"(x)); return r;
}
__device__ __forceinline__ uint32_t smem_u32(const void* p) {
    uint32_t a;
    asm("{ .reg .u64 t; cvta.to.shared.u64 t, %1; cvt.u32.u64 %0, t; }" : "=r"(a) : "l"(p));
    return a;
}
#define MBAR_INIT(a, n)  asm volatile("mbarrier.init.shared.b64 [%0], %1;" :: "r"(a), "r"((uint32_t)(n)) : "memory")
#define MBAR_EXPECT_TX(a, n) asm volatile("mbarrier.arrive.expect_tx.shared.b64 _, [%0], %1;" :: "r"(a), "r"((uint32_t)(n)) : "memory")
#define MBAR_WAIT(a, ph) do {                                                   \
    uint32_t _m = (a); uint32_t _p = (ph); uint32_t _d;                         \
    asm volatile("{\n\t.reg .pred p;\n\t"                                       \
        "mbarrier.try_wait.parity.acquire.cta.shared::cta.b64 p, [%1], %2;\n\t" \
        "selp.b32 %0, 1, 0, p;\n\t}" : "=r"(_d) : "r"(_m), "r"(_p) : "memory"); \
    if (!_d) {                                                                  \
        asm volatile("{\n\t.reg .pred P1;\n\t"                                  \
            "W%=:\n\t"                                                          \
            "mbarrier.try_wait.parity.acquire.cta.shared::cta.b64 P1, [%0], %1, 0x989680;\n\t" \
            "@P1 bra.uni D%=;\n\t"                                              \
            "bra.uni W%=;\n\t"                                                  \
            "D%=:\n\t}" :: "r"(_m), "r"(_p) : "memory");                        \
    } } while (0)
#define BULK_G2S(dst, src, bytes, mbar) \
    asm volatile("cp.async.bulk.shared::cluster.global.mbarrier::complete_tx::bytes [%0], [%1], %2, [%3];" \
        :: "r"(dst), "l"(src), "r"((uint32_t)(bytes)), "r"(mbar) : "memory")

__device__ __forceinline__ void mma8(float* d, const uint32_t* a, uint32_t b0, uint32_t b1) {
    asm volatile(
        "mma.sync.aligned.m16n8k8.row.col.f32.tf32.tf32.f32 "
        "{%0,%1,%2,%3}, {%4,%5,%6,%7}, {%8,%9}, {%0,%1,%2,%3};"
        : "+f"(d[0]), "+f"(d[1]), "+f"(d[2]), "+f"(d[3])
        : "r"(a[0]), "r"(a[1]), "r"(a[2]), "r"(a[3]), "r"(b0), "r"(b1));
}
__device__ __forceinline__ uint32_t f2u(float f) { return __float_as_uint(f); }

// -------- device scratch --------
__device__ float g_g2[N_PTS * M_DIM];
__device__ int   g_expert[N_PTS];
__device__ int   g_counts[E_EXP];
__device__ int   g_offsets[E_EXP + 1];
__device__ int   g_cursor[E_EXP];
__device__ int   g_perm[N_PTS];
// g1 activations, A-fragment-paired: [band512][ch14][GASLAB f2]
__device__ __align__(16) float g_g1p[(size_t)512 * GNCH * GASLAB * 2];
// gate W2, bulk-ready: [tile4][ch14][GBSLAB f2]
__device__ __align__(16) float g_W2t[4 * GNCH * GBSLAB * 2];
// siren weights paired: [e][l][ch6][SSLAB f2]
__device__ __align__(16) float g_Bws[E_EXP * NLAYER * SNCH * SSLAB * 2];

// ---------------- init ----------------
__global__ void k_init() {
    int t = threadIdx.x;
    if (t < E_EXP) g_counts[t] = 0;
}

// ---------------- g1 precompute (paired A layout) ----------------
__global__ void __launch_bounds__(256) k_g1(
    const float* __restrict__ x, const float* __restrict__ W1, const float* __restrict__ b1)
{
    __shared__ float xs[GM * 3];
    int band = blockIdx.x;
    for (int i = threadIdx.x; i < GM * 3; i += 256) xs[i] = tf32q(x[band * GM * 3 + i]);
    __syncthreads();
    float2* dst = ((float2*)g_g1p) + (size_t)band * (GNCH * GASLAB);
    for (int s = threadIdx.x; s < 56 * GM * 4; s += 256) {
        int c = s & 3, r = (s >> 2) & 127, kt = s >> 9;    // kt 0..55
        int k0 = kt * 8 + c;
        const float* xr = xs + r * 3;
        float2 v; v.x = 0.f; v.y = 0.f;
        if (k0 < M_DIM)
            v.x = tf32q(fmaxf(xr[0] * tf32q(W1[k0]) + xr[1] * tf32q(W1[M_DIM + k0])
                            + xr[2] * tf32q(W1[2 * M_DIM + k0]) + b1[k0], 0.f));
        int k1 = k0 + 4;
        if (k1 < M_DIM)
            v.y = tf32q(fmaxf(xr[0] * tf32q(W1[k1]) + xr[1] * tf32q(W1[M_DIM + k1])
                            + xr[2] * tf32q(W1[2 * M_DIM + k1]) + b1[k1], 0.f));
        dst[s] = v;
    }
}

// ---------------- weight preps ----------------
// W2 in bulk-ready per-tile layout: [tile][ch][ks4][c4][n GNPAD] float2
__global__ void k_prep_gateB(const float* __restrict__ W2) {
    float2* dst = (float2*)g_W2t;
    const int total = 4 * GNCH * GBSLAB;
    for (int s = blockIdx.x * blockDim.x + threadIdx.x; s < total;
         s += gridDim.x * blockDim.x) {
        int n = s % GNPAD;
        int c = (s / GNPAD) & 3;
        int ks = (s / (GNPAD * 4)) & 3;
        int ch = (s / (GNPAD * 16)) % GNCH;
        int tile = s / (GNPAD * 16 * GNCH);
        int k0 = (ch * 4 + ks) * 8 + c;
        int col = tile * GNT + n;
        float2 v; v.x = 0.f; v.y = 0.f;
        if (n < GNT && col < M_DIM) {
            if (k0 < M_DIM)     v.x = tf32q(W2[(size_t)k0 * M_DIM + col]);
            if (k0 + 4 < M_DIM) v.y = tf32q(W2[(size_t)(k0 + 4) * M_DIM + col]);
        }
        dst[s] = v;
    }
}
// siren weights, 8 blocks per (e,l)
__global__ void k_prep_siren(const float* __restrict__ sWh,
                             const float* __restrict__ sWo,
                             const float* __restrict__ dW1)
{
    int el = blockIdx.x >> 3;             // 0..39
    int part = blockIdx.x & 7;
    int e = el / NLAYER, l = el % NLAYER;
    const float* W;
    if (l < 3)       W = sWh + ((size_t)(l * E_EXP + e)) * F_DIM * F_DIM;
    else if (l == 3) W = sWo + (size_t)e * F_DIM * F_DIM;
    else             W = dW1 + (size_t)e * F_DIM * F_DIM;
    float2* dst = ((float2*)g_Bws) + (size_t)el * (SNCH * SSLAB);
    for (int s = part * 256 + threadIdx.x; s < SNCH * SSLAB; s += 2048) {
        int n = s % SNPAD, c = (s / SNPAD) & 3, ks = (s / (SNPAD * 4)) % 5, ch = s / SSLAB;
        int k0 = (ch * SKC + ks) * 8 + c;
        float2 v; v.x = 0.f; v.y = 0.f;
        if (n < F_DIM) {
            if (k0 < F_DIM)     v.x = tf32q(W[k0 * F_DIM + n]);
            if (k0 + 4 < F_DIM) v.y = tf32q(W[(k0 + 4) * F_DIM + n]);
        }
        dst[s] = v;
    }
}

// ---------------- gating GEMM (tf32 mma, bulk double-buffer) ----------------
__global__ void __launch_bounds__(256, 2) k_gate(const float* __restrict__ b2)
{
    extern __shared__ float smf[];
    float2* Af = (float2*)smf;                 // 2 x GASLAB
    float2* Bf = ((float2*)smf) + 2 * GASLAB;  // 2 x GBSLAB
    __shared__ __align__(8) unsigned long long mbar[2];
    const int tid = threadIdx.x;
    const int wid = tid >> 5, lane = tid & 31;
    const int r4 = lane >> 2, c4 = lane & 3;
    const int band = blockIdx.y;
    const int tile = blockIdx.x;
    const int wrow = (wid & 3) * 32;
    const int wcol = (wid >> 2) * 56;
    const uint32_t mb0 = smem_u32(&mbar[0]);

    const char* srcA = (const char*)g_g1p + (size_t)band * GNCH * (GASLAB * 8);
    const char* srcB = (const char*)g_W2t + (size_t)tile * GNCH * (GBSLAB * 8);

    float acc[2][7][4];
#pragma unroll
    for (int m = 0; m < 2; m++)
#pragma unroll
        for (int nb = 0; nb < 7; nb++)
#pragma unroll
            for (int j = 0; j < 4; j++) acc[m][nb][j] = 0.f;

    if (tid == 0) { MBAR_INIT(mb0, 1); MBAR_INIT(mb0 + 8, 1); }
    __syncthreads();
    if (tid == 0) {
        MBAR_EXPECT_TX(mb0, GBYTES);
        BULK_G2S(smem_u32(Af), srcA, GASLAB * 8, mb0);
        BULK_G2S(smem_u32(Bf), srcB, GBSLAB * 8, mb0);
    }

#pragma unroll 1
    for (int ch = 0; ch < GNCH; ch++) {
        const int s = ch & 1, ph = (ch >> 1) & 1;
        MBAR_WAIT(mb0 + 8 * s, ph);
        __syncthreads();
        if (ch + 1 < GNCH && tid == 0) {
            const int t = s ^ 1;
            MBAR_EXPECT_TX(mb0 + 8 * t, GBYTES);
            BULK_G2S(smem_u32(Af + t * GASLAB), srcA + (size_t)(ch + 1) * GASLAB * 8, GASLAB * 8, mb0 + 8 * t);
            BULK_G2S(smem_u32(Bf + t * GBSLAB), srcB + (size_t)(ch + 1) * GBSLAB * 8, GBSLAB * 8, mb0 + 8 * t);
        }
        const float2* Ab = Af + s * GASLAB;
        const float2* Bb = Bf + s * GBSLAB;
#pragma unroll
        for (int ks = 0; ks < GKC; ks++) {
            uint32_t a[2][4];
#pragma unroll
            for (int mb = 0; mb < 2; mb++) {
                int r = wrow + 16 * mb + r4;
                float2 p = Ab[(ks * GM + r) * 4 + c4];
                float2 q = Ab[(ks * GM + r + 8) * 4 + c4];
                a[mb][0] = f2u(p.x); a[mb][1] = f2u(q.x);
                a[mb][2] = f2u(p.y); a[mb][3] = f2u(q.y);
            }
#pragma unroll
            for (int nb = 0; nb < 7; nb++) {
                float2 b = Bb[(ks * 4 + c4) * GNPAD + wcol + nb * 8 + r4];
                mma8(acc[0][nb], a[0], f2u(b.x), f2u(b.y));
                mma8(acc[1][nb], a[1], f2u(b.x), f2u(b.y));
            }
        }
    }

    // epilogue: g2 = tf32q(relu(acc + b2))
#pragma unroll
    for (int mb = 0; mb < 2; mb++) {
        int r = band * GM + wrow + 16 * mb + r4;
#pragma unroll
        for (int nb = 0; nb < 7; nb++) {
            int col = tile * GNT + wcol + nb * 8 + 2 * c4;
            if (col < M_DIM) {
                g_g2[(size_t)r * M_DIM + col]       = tf32q(fmaxf(acc[mb][nb][0] + b2[col], 0.f));
                g_g2[(size_t)(r + 8) * M_DIM + col] = tf32q(fmaxf(acc[mb][nb][2] + b2[col], 0.f));
            }
            if (col + 1 < M_DIM) {
                g_g2[(size_t)r * M_DIM + col + 1]       = tf32q(fmaxf(acc[mb][nb][1] + b2[col + 1], 0.f));
                g_g2[(size_t)(r + 8) * M_DIM + col + 1] = tf32q(fmaxf(acc[mb][nb][3] + b2[col + 1], 0.f));
            }
        }
    }
}

// ---------------- logits + argmax ----------------
__global__ void __launch_bounds__(256) k_logits(
    const float* __restrict__ W3, const float* __restrict__ b3)
{
    int gw = (blockIdx.x * blockDim.x + threadIdx.x) >> 5;
    int lane = threadIdx.x & 31;
    if (gw >= N_PTS) return;
    const float* g = g_g2 + (size_t)gw * M_DIM;
    float acc[8];
#pragma unroll
    for (int e = 0; e < 8; e++) acc[e] = 0.f;
    for (int k = lane; k < M_DIM; k += 32) {
        float gv = g[k];
        const float4* w4 = reinterpret_cast<const float4*>(W3 + k * 8);
        float4 wa = w4[0], wb = w4[1];
        acc[0] = fmaf(gv, tf32q(wa.x), acc[0]);
        acc[1] = fmaf(gv, tf32q(wa.y), acc[1]);
        acc[2] = fmaf(gv, tf32q(wa.z), acc[2]);
        acc[3] = fmaf(gv, tf32q(wa.w), acc[3]);
        acc[4] = fmaf(gv, tf32q(wb.x), acc[4]);
        acc[5] = fmaf(gv, tf32q(wb.y), acc[5]);
        acc[6] = fmaf(gv, tf32q(wb.z), acc[6]);
        acc[7] = fmaf(gv, tf32q(wb.w), acc[7]);
    }
#pragma unroll
    for (int e = 0; e < 8; e++) {
#pragma unroll
        for (int s = 16; s > 0; s >>= 1)
            acc[e] += __shfl_xor_sync(0xffffffffu, acc[e], s);
    }
    if (lane == 0) {
        float best = acc[0] + b3[0]; int bi = 0;
#pragma unroll
        for (int e = 1; e < 8; e++) {
            float v = acc[e] + b3[e];
            if (v > best) { best = v; bi = e; }
        }
        g_expert[gw] = bi;
        atomicAdd(&g_counts[bi], 1);
    }
}

// ---------------- scan + KL (one-hot => constant) ----------------
__global__ void k_scan(float* out, int kl_idx) {
    if (threadIdx.x == 0) {
        int off = 0;
        for (int e = 0; e < E_EXP; e++) {
            g_offsets[e] = off;
            off += g_counts[e];
            g_cursor[e] = 0;
        }
        g_offsets[E_EXP] = off;
        out[kl_idx] = logf(0.125f) - 0.875f * logf(1e-10f);
    }
}

// ---------------- scatter ----------------
__global__ void k_scatter() {
    int n = blockIdx.x * blockDim.x + threadIdx.x;
    if (n >= N_PTS) return;
    int e = g_expert[n];
    int p = atomicAdd(&g_cursor[e], 1);
    g_perm[g_offsets[e] + p] = n;
}

// ---------------- fused SIREN + decoder (tf32 mma, bulk double-buffer) ----------------
__global__ void __launch_bounds__(256, 1) k_siren(
    const float* __restrict__ x,
    const float* __restrict__ sW1, const float* __restrict__ sb1,
    const float* __restrict__ sbh, const float* __restrict__ sbo,
    const float* __restrict__ db1,
    const float* __restrict__ dW2, const float* __restrict__ db2,
    float* __restrict__ out)
{
    extern __shared__ float smf[];
    float2* Af2 = (float2*)smf;              // 2 x SABUF
    float2* Bf2 = Af2 + 2 * SABUF;           // 2 x SSLAB
    __shared__ float xs[TMS * 3];
    __shared__ float part[4][TMS][3];
    __shared__ __align__(8) unsigned long long mbar[2];

    const int e = blockIdx.y;
    const int tid = threadIdx.x;
    const int wid = tid >> 5, lane = tid & 31;
    const int r4 = lane >> 2, c4 = lane & 3;
    const int beg = g_offsets[e], end = g_offsets[e + 1];
    const int start = beg + blockIdx.x * TMS;
    if (start >= end) return;
    const int npts = min(TMS, end - start);
    const uint32_t mb0 = smem_u32(&mbar[0]);

    const int wrow = (wid & 1) * 32;
    const int wcol = (wid >> 1) * 64;
    const char* bsrc = (const char*)g_Bws + (size_t)e * (NLAYER * SNCH) * SBYTES;

    if (tid == 0) { MBAR_INIT(mb0, 1); MBAR_INIT(mb0 + 8, 1); }
    if (tid < TMS) {
        float x0 = 0.f, x1 = 0.f, x2 = 0.f;
        if (tid < npts) {
            int n = g_perm[start + tid];
            x0 = tf32q(x[n * 3]); x1 = tf32q(x[n * 3 + 1]); x2 = tf32q(x[n * 3 + 2]);
        }
        xs[tid * 3] = x0; xs[tid * 3 + 1] = x1; xs[tid * 3 + 2] = x2;
    }
    __syncthreads();
    if (tid == 0) {
        MBAR_EXPECT_TX(mb0, SBYTES);
        BULK_G2S(smem_u32(Bf2), bsrc, SBYTES, mb0);
    }

    // first sine layer -> A buffer 0 (fragment-paired layout)
    {
        const float* W1e = sW1 + (size_t)e * 3 * F_DIM;
        const float* b1e = sb1 + (size_t)e * F_DIM;
        float* A0 = (float*)Af2;
        for (int idx = tid; idx < TMS * 240; idx += 256) {
            int row = idx / 240, col = idx - row * 240;
            float v = 0.f;
            if (col < F_DIM) {
                v = xs[row * 3] * tf32q(W1e[col])
                  + xs[row * 3 + 1] * tf32q(W1e[F_DIM + col])
                  + xs[row * 3 + 2] * tf32q(W1e[2 * F_DIM + col])
                  + b1e[col];
                v = tf32q(sinf(30.0f * v));
            }
            A0[(((col >> 3) * TMS + row) * 4 + (col & 3)) * 2 + ((col >> 2) & 1)] = v;
        }
    }
    __syncthreads();

    int ci = 0;
#pragma unroll 1
    for (int l = 0; l < NLAYER; l++) {
        const float2* Ab = Af2 + (l & 1) * SABUF;
        float* Cw = (float*)(Af2 + ((l & 1) ^ 1) * SABUF);

        float acc[2][8][4];
#pragma unroll
        for (int m = 0; m < 2; m++)
#pragma unroll
            for (int nb = 0; nb < 8; nb++)
#pragma unroll
                for (int j = 0; j < 4; j++) acc[m][nb][j] = 0.f;

#pragma unroll 1
        for (int chn = 0; chn < SNCH; chn++, ci++) {
            const int s = ci & 1, ph = (ci >> 1) & 1;
            MBAR_WAIT(mb0 + 8 * s, ph);
            __syncthreads();
            if (ci + 1 < NLAYER * SNCH && tid == 0) {
                const int t = s ^ 1;
                MBAR_EXPECT_TX(mb0 + 8 * t, SBYTES);
                BULK_G2S(smem_u32(Bf2 + t * SSLAB), bsrc + (size_t)(ci + 1) * SBYTES, SBYTES, mb0 + 8 * t);
            }
            const float2* Bb = Bf2 + s * SSLAB;
#pragma unroll
            for (int ksl = 0; ksl < SKC; ksl++) {
                int kg = chn * SKC + ksl;
                uint32_t a[2][4];
#pragma unroll
                for (int mb = 0; mb < 2; mb++) {
                    int r = wrow + 16 * mb + r4;
                    float2 p = Ab[(kg * TMS + r) * 4 + c4];
                    float2 q = Ab[(kg * TMS + r + 8) * 4 + c4];
                    a[mb][0] = f2u(p.x); a[mb][1] = f2u(q.x);
                    a[mb][2] = f2u(p.y); a[mb][3] = f2u(q.y);
                }
#pragma unroll
                for (int nb = 0; nb < 8; nb++) {
                    float2 b = Bb[(ksl * 4 + c4) * SNPAD + wcol + nb * 8 + r4];
                    mma8(acc[0][nb], a[0], f2u(b.x), f2u(b.y));
                    mma8(acc[1][nb], a[1], f2u(b.x), f2u(b.y));
                }
            }
        }

        if (l < 4) {
            // bias + activation -> next A buffer (fragment-paired layout)
            const float* bias = (l < 3) ? (sbh + (size_t)(l * E_EXP + e) * F_DIM)
                                        : (sbo + (size_t)e * F_DIM);
            __syncthreads();   // all MMA reads of Ab done before overwriting Cw? Cw != Ab; protects Cw reuse across layers
#pragma unroll
            for (int mb = 0; mb < 2; mb++) {
                int r = wrow + 16 * mb + r4;
#pragma unroll
                for (int nb = 0; nb < 8; nb++) {
                    int j0 = wcol + nb * 8 + 2 * c4;
                    if (j0 >= 240) continue;
                    int kt = j0 >> 3, cA = j0 & 3, h = (j0 >> 2) & 1;
#pragma unroll
                    for (int hr = 0; hr < 2; hr++) {
                        int row = r + 8 * hr;
                        float v0 = 0.f, v1 = 0.f;
                        if (j0 < F_DIM) {
                            v0 = acc[mb][nb][2 * hr] + bias[j0];
                            if (l < 3) v0 = sinf(30.0f * v0);
                            v0 = tf32q(v0);
                        }
                        if (j0 + 1 < F_DIM) {
                            v1 = acc[mb][nb][2 * hr + 1] + bias[j0 + 1];
                            if (l < 3) v1 = sinf(30.0f * v1);
                            v1 = tf32q(v1);
                        }
                        int base = ((kt * TMS + row) * 4 + cA) * 2 + h;
                        Cw[base] = v0;
                        Cw[base + 2] = v1;
                    }
                }
            }
            __syncthreads();
        } else {
            // dec1 (relu) + dec2 (236->3) fused from registers
            float s[4][3];
#pragma unroll
            for (int ri = 0; ri < 4; ri++)
#pragma unroll
                for (int o = 0; o < 3; o++) s[ri][o] = 0.f;
#pragma unroll
            for (int mb = 0; mb < 2; mb++) {
#pragma unroll
                for (int nb = 0; nb < 8; nb++) {
                    int j0 = wcol + nb * 8 + 2 * c4;
                    if (j0 >= F_DIM) continue;
#pragma unroll
                    for (int hr = 0; hr < 2; hr++) {
                        int ri = mb * 2 + hr;
                        float a0 = tf32q(fmaxf(acc[mb][nb][2 * hr] + db1[j0], 0.f));
                        s[ri][0] = fmaf(a0, tf32q(dW2[j0 * 3 + 0]), s[ri][0]);
                        s[ri][1] = fmaf(a0, tf32q(dW2[j0 * 3 + 1]), s[ri][1]);
                        s[ri][2] = fmaf(a0, tf32q(dW2[j0 * 3 + 2]), s[ri][2]);
                        if (j0 + 1 < F_DIM) {
                            float a1 = tf32q(fmaxf(acc[mb][nb][2 * hr + 1] + db1[j0 + 1], 0.f));
                            s[ri][0] = fmaf(a1, tf32q(dW2[(j0 + 1) * 3 + 0]), s[ri][0]);
                            s[ri][1] = fmaf(a1, tf32q(dW2[(j0 + 1) * 3 + 1]), s[ri][1]);
                            s[ri][2] = fmaf(a1, tf32q(dW2[(j0 + 1) * 3 + 2]), s[ri][2]);
                        }
                    }
                }
            }
#pragma unroll
            for (int ri = 0; ri < 4; ri++)
#pragma unroll
                for (int o = 0; o < 3; o++) {
                    float v = s[ri][o];
                    v += __shfl_xor_sync(0xffffffffu, v, 1);
                    v += __shfl_xor_sync(0xffffffffu, v, 2);
                    s[ri][o] = v;
                }
            int ng = wid >> 1;
            if (c4 == 0) {
#pragma unroll
                for (int ri = 0; ri < 4; ri++) {
                    int row = wrow + 16 * (ri >> 1) + r4 + 8 * (ri & 1);
#pragma unroll
                    for (int o = 0; o < 3; o++) part[ng][row][o] = s[ri][o];
                }
            }
            __syncthreads();
            if (tid < TMS * 3) {
                int p = tid / 3, o = tid - p * 3;
                if (p < npts) {
                    float v = db2[o] + part[0][p][o] + part[1][p][o]
                            + part[2][p][o] + part[3][p][o];
                    out[g_perm[start + p] * 3 + o] = v;
                }
            }
        }
    }
}

// ---------------- launch ----------------
extern "C" void kernel_launch(void* const* d_in, const int* in_sizes, int n_in,
                              void* d_out, int out_size)
{
    const float* x   = (const float*)d_in[0];
    const float* sW1 = (const float*)d_in[1];
    const float* sb1 = (const float*)d_in[2];
    const float* sWh = (const float*)d_in[3];
    const float* sbh = (const float*)d_in[4];
    const float* sWo = (const float*)d_in[5];
    const float* sbo = (const float*)d_in[6];
    const float* mW1 = (const float*)d_in[7];
    const float* mb1 = (const float*)d_in[8];
    const float* mW2 = (const float*)d_in[9];
    const float* mb2 = (const float*)d_in[10];
    const float* mW3 = (const float*)d_in[11];
    const float* mb3 = (const float*)d_in[12];
    const float* dW1 = (const float*)d_in[13];
    const float* db1 = (const float*)d_in[14];
    const float* dW2 = (const float*)d_in[15];
    const float* db2 = (const float*)d_in[16];
    float* out = (float*)d_out;

    size_t smem_gate  = (size_t)(2 * GASLAB + 2 * GBSLAB) * 8;  // 62464 B
    size_t smem_siren = (size_t)(2 * SABUF + 2 * SSLAB) * 8;    // 206080 B
    cudaFuncSetAttribute(k_gate,  cudaFuncAttributeMaxDynamicSharedMemorySize, (int)smem_gate);
    cudaFuncSetAttribute(k_siren, cudaFuncAttributeMaxDynamicSharedMemorySize, (int)smem_siren);

    k_init<<<1, 32>>>();
    k_g1<<<512, 256>>>(x, mW1, mb1);
    k_prep_gateB<<<256, 256>>>(mW2);
    k_prep_siren<<<E_EXP * NLAYER * 8, 256>>>(sWh, sWo, dW1);

    dim3 gG(4, 512);                         // (N tiles, bands)
    k_gate<<<gG, 256, smem_gate>>>(mb2);

    k_logits<<<(N_PTS * 32) / 256, 256>>>(mW3, mb3);

    k_scan<<<1, 32>>>(out, out_size - 1);

    k_scatter<<<N_PTS / 256, 256>>>();

    dim3 gS((N_PTS + TMS - 1) / TMS, E_EXP); // (1024, 8), extras exit
    k_siren<<<gS, 256, smem_siren>>>(x, sW1, sb1, sbh, sbo, db1, dW2, db2, out);
}